// round 5
// baseline (speedup 1.0000x reference)
#include <cuda_runtime.h>
#include <cuda_fp16.h>

// B=4, N=256, M=256, D=64. One CTA per (b,i) tile [256 rows, 64 dim].
// 256 threads = 8 warps; warp w owns rows [32w, 32w+32) processed as TWO
// sequential m16 passes to keep regs <= 128 so TWO CTAs co-reside per SM.
// GEMMs: mma.sync.aligned.m16n8k16; B-operands via ldmatrix.x4.

#define QS 72    // sQ row stride (halves)
#define WS 72    // weight row stride (halves)
#define VS 264   // sVt row stride (halves)

__device__ __forceinline__ void mma16(float4& d, const unsigned a[4], unsigned b0, unsigned b1) {
    asm("mma.sync.aligned.m16n8k16.row.col.f32.f16.f16.f32 "
        "{%0,%1,%2,%3},{%4,%5,%6,%7},{%8,%9},{%0,%1,%2,%3};"
        : "+f"(d.x), "+f"(d.y), "+f"(d.z), "+f"(d.w)
        : "r"(a[0]), "r"(a[1]), "r"(a[2]), "r"(a[3]), "r"(b0), "r"(b1));
}

__device__ __forceinline__ void ldsm4(unsigned& r0, unsigned& r1, unsigned& r2, unsigned& r3,
                                      const __half* p) {
    unsigned a = (unsigned)__cvta_generic_to_shared(p);
    asm volatile("ldmatrix.sync.aligned.m8n8.x4.shared.b16 {%0,%1,%2,%3},[%4];"
                 : "=r"(r0), "=r"(r1), "=r"(r2), "=r"(r3) : "r"(a));
}

__device__ __forceinline__ unsigned pack2(float lo, float hi) {
    __half2 h = __floats2half2_rn(lo, hi);
    return *reinterpret_cast<unsigned*>(&h);
}

__global__ void __launch_bounds__(256, 2)
pair_attn_v5(const float* __restrict__ x_all,
             const float* __restrict__ Wq, const float* __restrict__ bq,
             const float* __restrict__ Wk, const float* __restrict__ bk,
             const float* __restrict__ Wv, const float* __restrict__ bv,
             const float* __restrict__ Wo, const float* __restrict__ bo,
             const float* __restrict__ lng, const float* __restrict__ lnb,
             float* __restrict__ out_all)
{
    extern __shared__ __half sm[];
    __half* sQ  = sm;                    // [256][QS]  Q rows (1/8 scale folded)
    __half* sVt = sQ + 256 * QS;         // [64][VS]   V transposed: sVt[d][c]
    __half* sW  = sVt + 64 * VS;         // [4][64][WS]

    const int tid  = threadIdx.x;
    const int lane = tid & 31;
    const int wrp  = tid >> 5;
    const int g    = lane >> 2;
    const int t    = lane & 3;
    const int R0   = wrp * 32;
    const int lro  = ((lane >> 4) & 1) * 8 + (lane & 7);
    const int lco  = ((lane >> 3) & 1) * 8;

    const float* xg = x_all   + (size_t)blockIdx.x * 16384;
    float*       og = out_all + (size_t)blockIdx.x * 16384;

    // ---- stage all 4 weights as fp16 ----
    {
        const float* Wsrc[4] = {Wq, Wk, Wv, Wo};
        const int f  = tid >> 2;
        const int e0 = (tid & 3) * 16;
        #pragma unroll
        for (int w = 0; w < 4; w++) {
            const float* src = Wsrc[w] + f * 64 + e0;
            unsigned u[8];
            #pragma unroll
            for (int i = 0; i < 4; i++) {
                float4 p = *(const float4*)(src + 4 * i);
                u[2*i]   = pack2(p.x, p.y);
                u[2*i+1] = pack2(p.z, p.w);
            }
            *(uint4*)&sW[(w * 64 + f) * WS + e0]     = *(uint4*)&u[0];
            *(uint4*)&sW[(w * 64 + f) * WS + e0 + 8] = *(uint4*)&u[4];
        }
    }
    __syncthreads();

    // ---- projections: per m16 tile, one weight sweep at a time (low regs) ----
    unsigned ka[2][4][4];
    #pragma unroll
    for (int mt = 0; mt < 2; mt++) {
        const int rA = R0 + 16 * mt + g, rB = rA + 8;
        unsigned xa[4][4];
        #pragma unroll
        for (int kt = 0; kt < 4; kt++) {
            int c = 16 * kt + 2 * t;
            float2 v0 = *(const float2*)&xg[rA * 64 + c];
            float2 v1 = *(const float2*)&xg[rB * 64 + c];
            float2 v2 = *(const float2*)&xg[rA * 64 + c + 8];
            float2 v3 = *(const float2*)&xg[rB * 64 + c + 8];
            xa[kt][0] = pack2(v0.x, v0.y);
            xa[kt][1] = pack2(v1.x, v1.y);
            xa[kt][2] = pack2(v2.x, v2.y);
            xa[kt][3] = pack2(v3.x, v3.y);
        }
        // K sweep -> pack into ka[mt]
        {
            float4 d[8];
            #pragma unroll
            for (int nt = 0; nt < 8; nt++) d[nt] = make_float4(0.f, 0.f, 0.f, 0.f);
            #pragma unroll
            for (int kt = 0; kt < 4; kt++)
                #pragma unroll
                for (int j = 0; j < 4; j++) {
                    unsigned b0, b1, b2, b3;
                    ldsm4(b0, b1, b2, b3, &sW[(1 * 64 + 16 * j + lro) * WS + 16 * kt + lco]);
                    mma16(d[2*j],   xa[kt], b0, b1);
                    mma16(d[2*j+1], xa[kt], b2, b3);
                }
            #pragma unroll
            for (int nt = 0; nt < 8; nt++) {
                float2 bb = __ldg((const float2*)&bk[8 * nt + 2 * t]);
                d[nt].x += bb.x; d[nt].y += bb.y; d[nt].z += bb.x; d[nt].w += bb.y;
            }
            #pragma unroll
            for (int kt = 0; kt < 4; kt++) {
                ka[mt][kt][0] = pack2(d[2*kt].x,   d[2*kt].y);
                ka[mt][kt][1] = pack2(d[2*kt].z,   d[2*kt].w);
                ka[mt][kt][2] = pack2(d[2*kt+1].x, d[2*kt+1].y);
                ka[mt][kt][3] = pack2(d[2*kt+1].z, d[2*kt+1].w);
            }
        }
        // Q sweep -> sQ (1/8 folded)
        {
            float4 d[8];
            #pragma unroll
            for (int nt = 0; nt < 8; nt++) d[nt] = make_float4(0.f, 0.f, 0.f, 0.f);
            #pragma unroll
            for (int kt = 0; kt < 4; kt++)
                #pragma unroll
                for (int j = 0; j < 4; j++) {
                    unsigned b0, b1, b2, b3;
                    ldsm4(b0, b1, b2, b3, &sW[(0 * 64 + 16 * j + lro) * WS + 16 * kt + lco]);
                    mma16(d[2*j],   xa[kt], b0, b1);
                    mma16(d[2*j+1], xa[kt], b2, b3);
                }
            #pragma unroll
            for (int nt = 0; nt < 8; nt++) {
                int c = 8 * nt + 2 * t;
                float2 bb = __ldg((const float2*)&bq[c]);
                *(unsigned*)&sQ[rA * QS + c] = pack2((d[nt].x + bb.x) * 0.125f,
                                                     (d[nt].y + bb.y) * 0.125f);
                *(unsigned*)&sQ[rB * QS + c] = pack2((d[nt].z + bb.x) * 0.125f,
                                                     (d[nt].w + bb.y) * 0.125f);
            }
        }
        // V sweep -> sVt (transposed)
        {
            float4 d[8];
            #pragma unroll
            for (int nt = 0; nt < 8; nt++) d[nt] = make_float4(0.f, 0.f, 0.f, 0.f);
            #pragma unroll
            for (int kt = 0; kt < 4; kt++)
                #pragma unroll
                for (int j = 0; j < 4; j++) {
                    unsigned b0, b1, b2, b3;
                    ldsm4(b0, b1, b2, b3, &sW[(2 * 64 + 16 * j + lro) * WS + 16 * kt + lco]);
                    mma16(d[2*j],   xa[kt], b0, b1);
                    mma16(d[2*j+1], xa[kt], b2, b3);
                }
            #pragma unroll
            for (int nt = 0; nt < 8; nt++) {
                int c = 8 * nt + 2 * t;
                float2 bb = __ldg((const float2*)&bv[c]);
                sVt[(c)     * VS + rA] = __float2half_rn(d[nt].x + bb.x);
                sVt[(c + 1) * VS + rA] = __float2half_rn(d[nt].y + bb.y);
                sVt[(c)     * VS + rB] = __float2half_rn(d[nt].z + bb.x);
                sVt[(c + 1) * VS + rB] = __float2half_rn(d[nt].w + bb.y);
            }
        }
    }
    __syncthreads();   // sQ, sVt complete

    // ---- two m16 passes: mainloop + full epilogue per pass ----
    #pragma unroll
    for (int mt = 0; mt < 2; mt++) {
        const int rA = R0 + 16 * mt + g, rB = rA + 8;
        float4 ctx[8];
        #pragma unroll
        for (int nt = 0; nt < 8; nt++) ctx[nt] = make_float4(0.f, 0.f, 0.f, 0.f);
        float den0 = 0.f, den1 = 0.f;

        #pragma unroll 2
        for (int cb = 0; cb < 16; cb++) {
            float4 se = make_float4(0.f, 0.f, 0.f, 0.f), so = se;
            #pragma unroll
            for (int kt = 0; kt < 4; kt++) {
                unsigned q0, q1, q2, q3;
                ldsm4(q0, q1, q2, q3, &sQ[(16 * cb + lro) * QS + 16 * kt + lco]);
                mma16(se, ka[mt][kt], q0, q1);
                mma16(so, ka[mt][kt], q2, q3);
            }
            se.x = fmaxf(se.x, 0.f); se.y = fmaxf(se.y, 0.f);
            se.z = fmaxf(se.z, 0.f); se.w = fmaxf(se.w, 0.f);
            so.x = fmaxf(so.x, 0.f); so.y = fmaxf(so.y, 0.f);
            so.z = fmaxf(so.z, 0.f); so.w = fmaxf(so.w, 0.f);
            den0 += (se.x + se.y) + (so.x + so.y);
            den1 += (se.z + se.w) + (so.z + so.w);
            unsigned pa[4];
            pa[0] = pack2(se.x, se.y); pa[1] = pack2(se.z, se.w);
            pa[2] = pack2(so.x, so.y); pa[3] = pack2(so.z, so.w);
            #pragma unroll
            for (int j = 0; j < 4; j++) {
                unsigned v0, v1, v2, v3;
                ldsm4(v0, v1, v2, v3, &sVt[(16 * j + lro) * VS + 16 * cb + lco]);
                mma16(ctx[2*j],   pa, v0, v1);
                mma16(ctx[2*j+1], pa, v2, v3);
            }
        }

        // normalize (denom = sum(relu) + 256e-12)
        den0 += __shfl_xor_sync(0xffffffffu, den0, 1);
        den0 += __shfl_xor_sync(0xffffffffu, den0, 2);
        den1 += __shfl_xor_sync(0xffffffffu, den1, 1);
        den1 += __shfl_xor_sync(0xffffffffu, den1, 2);
        float inv0 = 1.0f / (den0 + 2.56e-10f);
        float inv1 = 1.0f / (den1 + 2.56e-10f);
        unsigned cf[4][4];
        #pragma unroll
        for (int nt = 0; nt < 8; nt++) {
            ctx[nt].x *= inv0; ctx[nt].y *= inv0;
            ctx[nt].z *= inv1; ctx[nt].w *= inv1;
        }
        #pragma unroll
        for (int kt = 0; kt < 4; kt++) {
            cf[kt][0] = pack2(ctx[2*kt].x,   ctx[2*kt].y);
            cf[kt][1] = pack2(ctx[2*kt].z,   ctx[2*kt].w);
            cf[kt][2] = pack2(ctx[2*kt+1].x, ctx[2*kt+1].y);
            cf[kt][3] = pack2(ctx[2*kt+1].z, ctx[2*kt+1].w);
        }

        // output projection
        float4 y[8];
        #pragma unroll
        for (int nt = 0; nt < 8; nt++) y[nt] = make_float4(0.f, 0.f, 0.f, 0.f);
        #pragma unroll
        for (int kt = 0; kt < 4; kt++)
            #pragma unroll
            for (int j = 0; j < 4; j++) {
                unsigned b0, b1, b2, b3;
                ldsm4(b0, b1, b2, b3, &sW[(3 * 64 + 16 * j + lro) * WS + 16 * kt + lco]);
                mma16(y[2*j],   cf[kt], b0, b1);
                mma16(y[2*j+1], cf[kt], b2, b3);
            }

        // residual + LayerNorm + store
        float s0 = 0.f, s1 = 0.f, q0 = 0.f, q1 = 0.f;
        #pragma unroll
        for (int nt = 0; nt < 8; nt++) {
            int c = 8 * nt + 2 * t;
            float2 bb = __ldg((const float2*)&bo[c]);
            float2 x0 = *(const float2*)&xg[rA * 64 + c];
            float2 x1 = *(const float2*)&xg[rB * 64 + c];
            y[nt].x += bb.x + x0.x; y[nt].y += bb.y + x0.y;
            y[nt].z += bb.x + x1.x; y[nt].w += bb.y + x1.y;
            s0 += y[nt].x + y[nt].y;  q0 += y[nt].x * y[nt].x + y[nt].y * y[nt].y;
            s1 += y[nt].z + y[nt].w;  q1 += y[nt].z * y[nt].z + y[nt].w * y[nt].w;
        }
        s0 += __shfl_xor_sync(0xffffffffu, s0, 1); s0 += __shfl_xor_sync(0xffffffffu, s0, 2);
        q0 += __shfl_xor_sync(0xffffffffu, q0, 1); q0 += __shfl_xor_sync(0xffffffffu, q0, 2);
        s1 += __shfl_xor_sync(0xffffffffu, s1, 1); s1 += __shfl_xor_sync(0xffffffffu, s1, 2);
        q1 += __shfl_xor_sync(0xffffffffu, q1, 1); q1 += __shfl_xor_sync(0xffffffffu, q1, 2);
        float mu0 = s0 * (1.f / 64.f), mu1 = s1 * (1.f / 64.f);
        float rs0 = rsqrtf(q0 * (1.f / 64.f) - mu0 * mu0 + 1e-5f);
        float rs1 = rsqrtf(q1 * (1.f / 64.f) - mu1 * mu1 + 1e-5f);
        #pragma unroll
        for (int nt = 0; nt < 8; nt++) {
            int c = 8 * nt + 2 * t;
            float2 gg = __ldg((const float2*)&lng[c]);
            float2 bb = __ldg((const float2*)&lnb[c]);
            *(float2*)&og[rA * 64 + c] = make_float2((y[nt].x - mu0) * rs0 * gg.x + bb.x,
                                                     (y[nt].y - mu0) * rs0 * gg.y + bb.y);
            *(float2*)&og[rB * 64 + c] = make_float2((y[nt].z - mu1) * rs1 * gg.x + bb.x,
                                                     (y[nt].w - mu1) * rs1 * gg.y + bb.y);
        }
    }
}

extern "C" void kernel_launch(void* const* d_in, const int* in_sizes, int n_in,
                              void* d_out, int out_size)
{
    const float* x   = (const float*)d_in[1];
    const float* Wq  = (const float*)d_in[2];
    const float* bq  = (const float*)d_in[3];
    const float* Wk  = (const float*)d_in[4];
    const float* bk  = (const float*)d_in[5];
    const float* Wv  = (const float*)d_in[6];
    const float* bv  = (const float*)d_in[7];
    const float* Wo  = (const float*)d_in[8];
    const float* bo  = (const float*)d_in[9];
    const float* lng = (const float*)d_in[10];
    const float* lnb = (const float*)d_in[11];
    float* out = (float*)d_out;

    int tiles = in_sizes[1] / (256 * 64);   // B*N = 1024
    size_t smem = (size_t)(256 * QS + 64 * VS + 4 * 64 * WS) * sizeof(__half); // 107520 B

    cudaFuncSetAttribute(pair_attn_v5,
                         cudaFuncAttributeMaxDynamicSharedMemorySize, (int)smem);

    pair_attn_v5<<<tiles, 256, smem>>>(x, Wq, bq, Wk, bk, Wv, bv, Wo, bo,
                                       lng, lnb, out);
}

// round 6
// speedup vs baseline: 1.0610x; 1.0610x over previous
#include <cuda_runtime.h>
#include <cuda_fp16.h>

// B=4, N=256, M=256, D=64. One CTA per (b,i) tile [256 rows, 64 dim].
// 256 threads = 8 warps; warp w owns rows [32w, 32w+32) as TWO m16 tiles
// (shared B-fragments: 4 MMAs per ldmatrix.x4). Register-dieted so that
// TWO CTAs co-reside per SM (regs<=128, smem=96KB).

#define QS 72    // sQ row stride (halves)
#define WS 72    // weight row stride (halves)
#define VS 264   // sVt row stride (halves)

__device__ __forceinline__ void mma16(float4& d, const unsigned a[4], unsigned b0, unsigned b1) {
    asm("mma.sync.aligned.m16n8k16.row.col.f32.f16.f16.f32 "
        "{%0,%1,%2,%3},{%4,%5,%6,%7},{%8,%9},{%0,%1,%2,%3};"
        : "+f"(d.x), "+f"(d.y), "+f"(d.z), "+f"(d.w)
        : "r"(a[0]), "r"(a[1]), "r"(a[2]), "r"(a[3]), "r"(b0), "r"(b1));
}

__device__ __forceinline__ void ldsm4(unsigned& r0, unsigned& r1, unsigned& r2, unsigned& r3,
                                      const __half* p) {
    unsigned a = (unsigned)__cvta_generic_to_shared(p);
    asm volatile("ldmatrix.sync.aligned.m8n8.x4.shared.b16 {%0,%1,%2,%3},[%4];"
                 : "=r"(r0), "=r"(r1), "=r"(r2), "=r"(r3) : "r"(a));
}

__device__ __forceinline__ unsigned pack2(float lo, float hi) {
    __half2 h = __floats2half2_rn(lo, hi);
    return *reinterpret_cast<unsigned*>(&h);
}

// Stage one 64x64 fp32 weight into an fp16 smem slot (thread: row tid/4, 16-col run).
__device__ __forceinline__ void stageW(const float* __restrict__ W, __half* dst, int tid) {
    const int f  = tid >> 2;
    const int e0 = (tid & 3) * 16;
    const float* src = W + f * 64 + e0;
    unsigned u[8];
    #pragma unroll
    for (int i = 0; i < 4; i++) {
        float4 p = *(const float4*)(src + 4 * i);
        u[2*i]   = pack2(p.x, p.y);
        u[2*i+1] = pack2(p.z, p.w);
    }
    *(uint4*)&dst[f * WS + e0]     = *(uint4*)&u[0];
    *(uint4*)&dst[f * WS + e0 + 8] = *(uint4*)&u[4];
}

__global__ void __launch_bounds__(256, 2)
pair_attn_v6(const float* __restrict__ x_all,
             const float* __restrict__ Wq, const float* __restrict__ bq,
             const float* __restrict__ Wk, const float* __restrict__ bk,
             const float* __restrict__ Wv, const float* __restrict__ bv,
             const float* __restrict__ Wo, const float* __restrict__ bo,
             const float* __restrict__ lng, const float* __restrict__ lnb,
             float* __restrict__ out_all)
{
    extern __shared__ __half sm[];
    __half* sQ  = sm;                    // [256][QS]  Q rows (1/8 scale folded)
    __half* sVt = sQ + 256 * QS;         // [64][VS]   V transposed: sVt[d][c]
    __half* sW  = sVt + 64 * VS;         // [3][64][WS] slots: 0=Wq(->Wo), 1=Wk, 2=Wv

    const int tid  = threadIdx.x;
    const int lane = tid & 31;
    const int wrp  = tid >> 5;
    const int g    = lane >> 2;
    const int t    = lane & 3;
    const int R0   = wrp * 32;
    const int lro  = ((lane >> 4) & 1) * 8 + (lane & 7);
    const int lco  = ((lane >> 3) & 1) * 8;

    const float* xg = x_all   + (size_t)blockIdx.x * 16384;
    float*       og = out_all + (size_t)blockIdx.x * 16384;

    // ---- stage Wq, Wk, Wv ----
    stageW(Wq, sW + 0 * 64 * WS, tid);
    stageW(Wk, sW + 1 * 64 * WS, tid);
    stageW(Wv, sW + 2 * 64 * WS, tid);
    __syncthreads();

    // ---- projections: per m16 tile, one single-accumulator sweep per weight ----
    unsigned ka[2][4][4];
    #pragma unroll
    for (int mt = 0; mt < 2; mt++) {
        const int rA = R0 + 16 * mt + g, rB = rA + 8;
        unsigned xa[4][4];
        #pragma unroll
        for (int kt = 0; kt < 4; kt++) {
            int c = 16 * kt + 2 * t;
            float2 v0 = *(const float2*)&xg[rA * 64 + c];
            float2 v1 = *(const float2*)&xg[rB * 64 + c];
            float2 v2 = *(const float2*)&xg[rA * 64 + c + 8];
            float2 v3 = *(const float2*)&xg[rB * 64 + c + 8];
            xa[kt][0] = pack2(v0.x, v0.y);
            xa[kt][1] = pack2(v1.x, v1.y);
            xa[kt][2] = pack2(v2.x, v2.y);
            xa[kt][3] = pack2(v3.x, v3.y);
        }
        // K sweep (slot 1) -> ka[mt]
        {
            float4 d[8];
            #pragma unroll
            for (int nt = 0; nt < 8; nt++) d[nt] = make_float4(0.f, 0.f, 0.f, 0.f);
            #pragma unroll
            for (int kt = 0; kt < 4; kt++)
                #pragma unroll
                for (int j = 0; j < 4; j++) {
                    unsigned b0, b1, b2, b3;
                    ldsm4(b0, b1, b2, b3, &sW[(1 * 64 + 16 * j + lro) * WS + 16 * kt + lco]);
                    mma16(d[2*j],   xa[kt], b0, b1);
                    mma16(d[2*j+1], xa[kt], b2, b3);
                }
            #pragma unroll
            for (int nt = 0; nt < 8; nt++) {
                float2 bb = __ldg((const float2*)&bk[8 * nt + 2 * t]);
                d[nt].x += bb.x; d[nt].y += bb.y; d[nt].z += bb.x; d[nt].w += bb.y;
            }
            #pragma unroll
            for (int kt = 0; kt < 4; kt++) {
                ka[mt][kt][0] = pack2(d[2*kt].x,   d[2*kt].y);
                ka[mt][kt][1] = pack2(d[2*kt].z,   d[2*kt].w);
                ka[mt][kt][2] = pack2(d[2*kt+1].x, d[2*kt+1].y);
                ka[mt][kt][3] = pack2(d[2*kt+1].z, d[2*kt+1].w);
            }
        }
        // Q sweep (slot 0) -> sQ (1/8 folded)
        {
            float4 d[8];
            #pragma unroll
            for (int nt = 0; nt < 8; nt++) d[nt] = make_float4(0.f, 0.f, 0.f, 0.f);
            #pragma unroll
            for (int kt = 0; kt < 4; kt++)
                #pragma unroll
                for (int j = 0; j < 4; j++) {
                    unsigned b0, b1, b2, b3;
                    ldsm4(b0, b1, b2, b3, &sW[(0 * 64 + 16 * j + lro) * WS + 16 * kt + lco]);
                    mma16(d[2*j],   xa[kt], b0, b1);
                    mma16(d[2*j+1], xa[kt], b2, b3);
                }
            #pragma unroll
            for (int nt = 0; nt < 8; nt++) {
                int c = 8 * nt + 2 * t;
                float2 bb = __ldg((const float2*)&bq[c]);
                *(unsigned*)&sQ[rA * QS + c] = pack2((d[nt].x + bb.x) * 0.125f,
                                                     (d[nt].y + bb.y) * 0.125f);
                *(unsigned*)&sQ[rB * QS + c] = pack2((d[nt].z + bb.x) * 0.125f,
                                                     (d[nt].w + bb.y) * 0.125f);
            }
        }
        // V sweep (slot 2) -> sVt (transposed)
        {
            float4 d[8];
            #pragma unroll
            for (int nt = 0; nt < 8; nt++) d[nt] = make_float4(0.f, 0.f, 0.f, 0.f);
            #pragma unroll
            for (int kt = 0; kt < 4; kt++)
                #pragma unroll
                for (int j = 0; j < 4; j++) {
                    unsigned b0, b1, b2, b3;
                    ldsm4(b0, b1, b2, b3, &sW[(2 * 64 + 16 * j + lro) * WS + 16 * kt + lco]);
                    mma16(d[2*j],   xa[kt], b0, b1);
                    mma16(d[2*j+1], xa[kt], b2, b3);
                }
            #pragma unroll
            for (int nt = 0; nt < 8; nt++) {
                int c = 8 * nt + 2 * t;
                float2 bb = __ldg((const float2*)&bv[c]);
                sVt[(c)     * VS + rA] = __float2half_rn(d[nt].x + bb.x);
                sVt[(c + 1) * VS + rA] = __float2half_rn(d[nt].y + bb.y);
                sVt[(c)     * VS + rB] = __float2half_rn(d[nt].z + bb.x);
                sVt[(c + 1) * VS + rB] = __float2half_rn(d[nt].w + bb.y);
            }
        }
    }
    __syncthreads();   // sQ/sVt complete; Wq/Wk/Wv dead

    // ---- stage Wo into slot 0 (mainloop never touches sW) ----
    stageW(Wo, sW + 0 * 64 * WS, tid);

    // ---- mainloop: S -> relu -> pack -> PV over 16 c-blocks (4 MMAs per LDSM) ----
    float4 ctx[2][8];
    #pragma unroll
    for (int mt = 0; mt < 2; mt++)
        #pragma unroll
        for (int nt = 0; nt < 8; nt++) ctx[mt][nt] = make_float4(0.f, 0.f, 0.f, 0.f);
    float den[2][2] = {{0.f, 0.f}, {0.f, 0.f}};

    #pragma unroll 1
    for (int cb = 0; cb < 16; cb++) {
        float4 s[2][2];
        s[0][0] = make_float4(0.f, 0.f, 0.f, 0.f);
        s[0][1] = s[0][0]; s[1][0] = s[0][0]; s[1][1] = s[0][0];
        #pragma unroll
        for (int kt = 0; kt < 4; kt++) {
            unsigned q0, q1, q2, q3;
            ldsm4(q0, q1, q2, q3, &sQ[(16 * cb + lro) * QS + 16 * kt + lco]);
            mma16(s[0][0], ka[0][kt], q0, q1);
            mma16(s[0][1], ka[0][kt], q2, q3);
            mma16(s[1][0], ka[1][kt], q0, q1);
            mma16(s[1][1], ka[1][kt], q2, q3);
        }
        unsigned pa[2][4];
        #pragma unroll
        for (int mt = 0; mt < 2; mt++) {
            float ex = fmaxf(s[mt][0].x, 0.f), ey = fmaxf(s[mt][0].y, 0.f);
            float ez = fmaxf(s[mt][0].z, 0.f), ew = fmaxf(s[mt][0].w, 0.f);
            float ox = fmaxf(s[mt][1].x, 0.f), oy = fmaxf(s[mt][1].y, 0.f);
            float oz = fmaxf(s[mt][1].z, 0.f), ow = fmaxf(s[mt][1].w, 0.f);
            den[mt][0] += (ex + ey) + (ox + oy);
            den[mt][1] += (ez + ew) + (oz + ow);
            pa[mt][0] = pack2(ex, ey); pa[mt][1] = pack2(ez, ew);
            pa[mt][2] = pack2(ox, oy); pa[mt][3] = pack2(oz, ow);
        }
        #pragma unroll
        for (int j = 0; j < 4; j++) {
            unsigned v0, v1, v2, v3;
            ldsm4(v0, v1, v2, v3, &sVt[(16 * j + lro) * VS + 16 * cb + lco]);
            mma16(ctx[0][2*j],   pa[0], v0, v1);
            mma16(ctx[0][2*j+1], pa[0], v2, v3);
            mma16(ctx[1][2*j],   pa[1], v0, v1);
            mma16(ctx[1][2*j+1], pa[1], v2, v3);
        }
    }
    __syncthreads();   // Wo staged (placed after mainloop; mainloop reads no sW)

    // ---- per-m-tile epilogue: normalize -> O-proj -> residual+LN -> store ----
    #pragma unroll
    for (int mt = 0; mt < 2; mt++) {
        const int rA = R0 + 16 * mt + g, rB = rA + 8;
        float d0 = den[mt][0], d1 = den[mt][1];
        d0 += __shfl_xor_sync(0xffffffffu, d0, 1);
        d0 += __shfl_xor_sync(0xffffffffu, d0, 2);
        d1 += __shfl_xor_sync(0xffffffffu, d1, 1);
        d1 += __shfl_xor_sync(0xffffffffu, d1, 2);
        float inv0 = 1.0f / (d0 + 2.56e-10f);
        float inv1 = 1.0f / (d1 + 2.56e-10f);
        unsigned cf[4][4];
        #pragma unroll
        for (int kt = 0; kt < 4; kt++) {
            cf[kt][0] = pack2(ctx[mt][2*kt].x * inv0,   ctx[mt][2*kt].y * inv0);
            cf[kt][1] = pack2(ctx[mt][2*kt].z * inv1,   ctx[mt][2*kt].w * inv1);
            cf[kt][2] = pack2(ctx[mt][2*kt+1].x * inv0, ctx[mt][2*kt+1].y * inv0);
            cf[kt][3] = pack2(ctx[mt][2*kt+1].z * inv1, ctx[mt][2*kt+1].w * inv1);
        }
        float4 y[8];
        #pragma unroll
        for (int nt = 0; nt < 8; nt++) y[nt] = make_float4(0.f, 0.f, 0.f, 0.f);
        #pragma unroll
        for (int kt = 0; kt < 4; kt++)
            #pragma unroll
            for (int j = 0; j < 4; j++) {
                unsigned b0, b1, b2, b3;
                ldsm4(b0, b1, b2, b3, &sW[(0 * 64 + 16 * j + lro) * WS + 16 * kt + lco]);
                mma16(y[2*j],   cf[kt], b0, b1);
                mma16(y[2*j+1], cf[kt], b2, b3);
            }
        float s0 = 0.f, s1 = 0.f, q0 = 0.f, q1 = 0.f;
        #pragma unroll
        for (int nt = 0; nt < 8; nt++) {
            int c = 8 * nt + 2 * t;
            float2 bb = __ldg((const float2*)&bo[c]);
            float2 x0 = *(const float2*)&xg[rA * 64 + c];
            float2 x1 = *(const float2*)&xg[rB * 64 + c];
            y[nt].x += bb.x + x0.x; y[nt].y += bb.y + x0.y;
            y[nt].z += bb.x + x1.x; y[nt].w += bb.y + x1.y;
            s0 += y[nt].x + y[nt].y;  q0 += y[nt].x * y[nt].x + y[nt].y * y[nt].y;
            s1 += y[nt].z + y[nt].w;  q1 += y[nt].z * y[nt].z + y[nt].w * y[nt].w;
        }
        s0 += __shfl_xor_sync(0xffffffffu, s0, 1); s0 += __shfl_xor_sync(0xffffffffu, s0, 2);
        q0 += __shfl_xor_sync(0xffffffffu, q0, 1); q0 += __shfl_xor_sync(0xffffffffu, q0, 2);
        s1 += __shfl_xor_sync(0xffffffffu, s1, 1); s1 += __shfl_xor_sync(0xffffffffu, s1, 2);
        q1 += __shfl_xor_sync(0xffffffffu, q1, 1); q1 += __shfl_xor_sync(0xffffffffu, q1, 2);
        float mu0 = s0 * (1.f / 64.f), mu1 = s1 * (1.f / 64.f);
        float rs0 = rsqrtf(q0 * (1.f / 64.f) - mu0 * mu0 + 1e-5f);
        float rs1 = rsqrtf(q1 * (1.f / 64.f) - mu1 * mu1 + 1e-5f);
        #pragma unroll
        for (int nt = 0; nt < 8; nt++) {
            int c = 8 * nt + 2 * t;
            float2 gg = __ldg((const float2*)&lng[c]);
            float2 bb = __ldg((const float2*)&lnb[c]);
            *(float2*)&og[rA * 64 + c] = make_float2((y[nt].x - mu0) * rs0 * gg.x + bb.x,
                                                     (y[nt].y - mu0) * rs0 * gg.y + bb.y);
            *(float2*)&og[rB * 64 + c] = make_float2((y[nt].z - mu1) * rs1 * gg.x + bb.x,
                                                     (y[nt].w - mu1) * rs1 * gg.y + bb.y);
        }
    }
}

extern "C" void kernel_launch(void* const* d_in, const int* in_sizes, int n_in,
                              void* d_out, int out_size)
{
    const float* x   = (const float*)d_in[1];
    const float* Wq  = (const float*)d_in[2];
    const float* bq  = (const float*)d_in[3];
    const float* Wk  = (const float*)d_in[4];
    const float* bk  = (const float*)d_in[5];
    const float* Wv  = (const float*)d_in[6];
    const float* bv  = (const float*)d_in[7];
    const float* Wo  = (const float*)d_in[8];
    const float* bo  = (const float*)d_in[9];
    const float* lng = (const float*)d_in[10];
    const float* lnb = (const float*)d_in[11];
    float* out = (float*)d_out;

    int tiles = in_sizes[1] / (256 * 64);   // B*N = 1024
    size_t smem = (size_t)(256 * QS + 64 * VS + 3 * 64 * WS) * sizeof(__half); // 98304 B

    cudaFuncSetAttribute(pair_attn_v6,
                         cudaFuncAttributeMaxDynamicSharedMemorySize, (int)smem);

    pair_attn_v6<<<tiles, 256, smem>>>(x, Wq, bq, Wk, bk, Wv, bv, Wo, bo,
                                       lng, lnb, out);
}